// round 3
// baseline (speedup 1.0000x reference)
#include <cuda_runtime.h>
#include <cuda_pipeline.h>

// RWKV WKV recurrence, B=16, T=2048, D=1024 fp32.
//   a_t = exp(w_t)*a_{t-1} + exp(k_t)
//   b_t = exp(w_t)*b_{t-1} + exp(k_t)*v_t
//   out_t = b_t / a_t
//
// One thread per (batch, d) channel; block = 128 contiguous channels, so a
// timestep slice per tensor is a contiguous 512B row. Loads are decoupled
// from the serial recurrence via an 8-stage cp.async SMEM pipeline
// (8 stages x 24KB = 192KB in flight per SM >> per-SM BDP share), making the
// kernel a pure DRAM stream instead of per-warp latency-bound.

#define TT   2048
#define DD   1024
#define UU   16                 // timesteps per stage
#define STG_ 8                  // pipeline depth
#define CH   128                // channels per block
#define NSTG (TT / UU)          // 128 stages

extern __shared__ float sm[];   // [STG_][3][UU][CH]

__global__ void __launch_bounds__(128, 1)
wkv_kernel(const float* __restrict__ k,
           const float* __restrict__ v,
           const float* __restrict__ w,
           float* __restrict__ out)
{
    const int tid  = threadIdx.x;
    const int warp = tid >> 5;
    const int lane = tid & 31;
    const int bi   = blockIdx.x >> 3;          // batch index (8 blocks per batch)
    const int d0   = (blockIdx.x & 7) * CH;    // channel base within D
    const long base = (long)bi * TT * DD + d0;

    const float* gk = k + base;
    const float* gv = v + base;
    const float* gw = w + base;
    float*       go = out + base;

    // Issue one stage: 48 rows (3 tensors x UU steps), each row 512B moved by
    // 32 lanes x 16B. 12 LDGSTS.128 per thread, one commit group per stage.
    auto issue_stage = [&](int t0, int slot) {
#pragma unroll
        for (int jj = 0; jj < 12; jj++) {
            const int j      = warp * 12 + jj;      // 0..47
            const int tensor = j >> 4;              // 0..2
            const int i      = j & 15;              // timestep within stage
            const float* bp  = (tensor == 0) ? gk : ((tensor == 1) ? gv : gw);
            const float* src = bp + (long)(t0 + i) * DD + lane * 4;
            float*       dst = sm + (((slot * 3 + tensor) * UU + i) * CH) + lane * 4;
            __pipeline_memcpy_async(dst, src, 16);
        }
        __pipeline_commit();
    };

    // Prologue: fill the pipeline.
#pragma unroll
    for (int s = 0; s < STG_; s++)
        issue_stage(s * UU, s);

    float a = 0.0f, b = 0.0f;

    for (int s = 0; s < NSTG; s++) {
        // Group-count invariant: exactly one commit per iteration (+8 in the
        // prologue), so wait_prior(STG_-1) guarantees group s is complete.
        __pipeline_wait_prior(STG_ - 1);
        __syncthreads();                       // make stage s visible to all

        const int   slot = s & (STG_ - 1);
        const float* sk = sm + ((slot * 3 + 0) * UU) * CH + tid;
        const float* sv = sm + ((slot * 3 + 1) * UU) * CH + tid;
        const float* sw = sm + ((slot * 3 + 2) * UU) * CH + tid;
        float* o = go + (long)(s * UU) * DD + tid;

#pragma unroll
        for (int i = 0; i < UU; i++) {
            const float kk = sk[i * CH];
            const float vv = sv[i * CH];
            const float ww = sw[i * CH];
            const float ew = __expf(ww);
            const float ek = __expf(kk);
            a = fmaf(ew, a, ek);
            b = fmaf(ew, b, ek * vv);
            o[i * DD] = __fdividef(b, a);
        }

        __syncthreads();                       // all done reading this slot
        if (s + STG_ < NSTG)
            issue_stage((s + STG_) * UU, slot);
        else
            __pipeline_commit();               // empty group keeps invariant
    }
}

extern "C" void kernel_launch(void* const* d_in, const int* in_sizes, int n_in,
                              void* d_out, int out_size)
{
    const float* k = (const float*)d_in[0];
    const float* v = (const float*)d_in[1];
    const float* w = (const float*)d_in[2];
    float* out = (float*)d_out;

    const int smem_bytes = STG_ * 3 * UU * CH * (int)sizeof(float);  // 196608
    cudaFuncSetAttribute(wkv_kernel,
                         cudaFuncAttributeMaxDynamicSharedMemorySize, smem_bytes);

    // 16384 channels / 128 per block = 128 blocks, one per SM.
    wkv_kernel<<<128, 128, smem_bytes>>>(k, v, w, out);
}